// round 15
// baseline (speedup 1.0000x reference)
#include <cuda_runtime.h>
#include <cstdint>

#define NS   1024      // n_states
#define NT   8192      // T; NT-1 = 8191 steps
#define NO   256       // n_out
#define NBLK 128       // persistent blocks
#define NTHR 256       // threads per block
#define RPB  8         // rows per block

// k-value buffers (6 rotating stages) + per-block release/acquire flags.
// Flags PACKED contiguously: a polling warp's 16 distinct flags span 64B ->
// the coalescer merges each poll sweep into 1-2 L2 transactions (vs 16
// separate lines at FSTRIDE=32 in R10 -> ~16K line-req/sweep chip-wide).
__device__ __align__(16) float g_k[6][NS];
__device__ __align__(16) unsigned int g_flag[NBLK];

__global__ void init_kernel() {
    if (threadIdx.x < NBLK) g_flag[threadIdx.x] = 0u;
}

// Pad launches: ncu captures launch index 3; order [pad, pad, init, ode, gemm]
// puts ode_kernel there (verified R12/R13).
__global__ void ncu_pad_kernel() {}

// Acquire-spin until producer flag >= sc (strong gpu-scope op: L2-serviced,
// cannot read stale L1; acquire orders the subsequent __ldcg value loads).
__device__ __forceinline__ void wait_flag(const unsigned int* f, unsigned sc) {
    unsigned v;
    do {
        asm volatile("ld.acquire.gpu.global.u32 %0, [%1];"
                     : "=r"(v) : "l"(f) : "memory");
    } while (v < sc);
}

__global__ void __launch_bounds__(NTHR, 1)
ode_kernel(const float* __restrict__ x0, const float* __restrict__ t,
           const float* __restrict__ A, float* __restrict__ xs)
{
    __shared__ float ty_sm[NS];
    __shared__ __align__(16) float kcol[RPB];

    const int tid = threadIdx.x;
    const int b   = blockIdx.x;
    const int w   = tid >> 5;        // warp = local row
    const int l   = tid & 31;
    const int R   = b * RPB + w;     // global row this warp produces
    const int j0  = tid * 4;         // 4 owned state indices (rows 4t..4t+3)

    // Producer block of this thread's 4 entries: (4t)/8 == t/2 (all 4 same).
    const unsigned int* myflag = &g_flag[tid >> 1];

    const float dt = __ldg(&t[1]) - __ldg(&t[0]);

    float a[32];
#pragma unroll
    for (int i = 0; i < 32; i++) a[i] = __ldg(&A[R * NS + l + 32 * i]);

    float4 xv = *reinterpret_cast<const float4*>(&x0[j0]);
    float xr[4] = {xv.x, xv.y, xv.z, xv.w};
    float k0[4], k1[4], k2[4], k3[4], k4[4], k5[4];

    if ((tid >> 1) == b) *reinterpret_cast<float4*>(&xs[j0]) = xv;

    unsigned sc = 0;   // monotonic stage counter; publish tag = sc after ++

    // tanh -> ty_sm; BAR; matvec; warp reduce; lane0 -> kcol; BAR;
    // thread0 alone: store 8 k values then st.release flag = sc.
    // Single-thread release ordering (the proven R10 idiom, unchanged).
#define STAGE_BODY(Y0, Y1, Y2, Y3) do {                                     \
        float4 tv;                                                          \
        tv.x = tanhf(Y0); tv.y = tanhf(Y1);                                 \
        tv.z = tanhf(Y2); tv.w = tanhf(Y3);                                 \
        *reinterpret_cast<float4*>(&ty_sm[j0]) = tv;                        \
        __syncthreads();                                                    \
        float acc0 = 0.f, acc1 = 0.f, acc2 = 0.f, acc3 = 0.f;               \
        _Pragma("unroll")                                                   \
        for (int i = 0; i < 32; i += 4) {                                   \
            acc0 = fmaf(a[i + 0], ty_sm[l + 32 * (i + 0)], acc0);           \
            acc1 = fmaf(a[i + 1], ty_sm[l + 32 * (i + 1)], acc1);           \
            acc2 = fmaf(a[i + 2], ty_sm[l + 32 * (i + 2)], acc2);           \
            acc3 = fmaf(a[i + 3], ty_sm[l + 32 * (i + 3)], acc3);           \
        }                                                                   \
        float acc = (acc0 + acc1) + (acc2 + acc3);                          \
        _Pragma("unroll")                                                   \
        for (int o = 16; o > 0; o >>= 1)                                    \
            acc += __shfl_down_sync(0xffffffffu, acc, o);                   \
        if (l == 0) kcol[w] = acc;                                          \
        __syncthreads();                                                    \
        sc++;                                                               \
        if (tid == 0) {                                                     \
            int S = (int)((sc - 1) % 6u);                                   \
            float4 v0 = *reinterpret_cast<float4*>(&kcol[0]);               \
            float4 v1 = *reinterpret_cast<float4*>(&kcol[4]);               \
            *reinterpret_cast<float4*>(&g_k[S][b * RPB])     = v0;          \
            *reinterpret_cast<float4*>(&g_k[S][b * RPB + 4]) = v1;          \
            asm volatile("st.release.gpu.global.u32 [%0], %1;"              \
                         :: "l"(&g_flag[b]), "r"(sc) : "memory");           \
        }                                                                   \
    } while (0)

#define LOADK(KR, S) do {                                                   \
        wait_flag(myflag, sc);                                              \
        float4 kv = __ldcg(reinterpret_cast<const float4*>(&g_k[S][j0]));   \
        KR[0] = kv.x; KR[1] = kv.y; KR[2] = kv.z; KR[3] = kv.w;             \
    } while (0)

    for (int step = 0; step < NT - 1; step++) {
        // stage 1: y = x
        STAGE_BODY(xr[0], xr[1], xr[2], xr[3]);

        // stage 2
        LOADK(k0, 0);
        {
            float y[4];
#pragma unroll
            for (int e = 0; e < 4; e++)
                y[e] = fmaf(dt, 0.2f * k0[e], xr[e]);
            STAGE_BODY(y[0], y[1], y[2], y[3]);
        }

        // stage 3
        LOADK(k1, 1);
        {
            float y[4];
#pragma unroll
            for (int e = 0; e < 4; e++) {
                float acc = (3.0f / 40.0f) * k0[e];
                acc = fmaf(9.0f / 40.0f, k1[e], acc);
                y[e] = fmaf(dt, acc, xr[e]);
            }
            STAGE_BODY(y[0], y[1], y[2], y[3]);
        }

        // stage 4
        LOADK(k2, 2);
        {
            float y[4];
#pragma unroll
            for (int e = 0; e < 4; e++) {
                float acc = (44.0f / 45.0f) * k0[e];
                acc = fmaf(-56.0f / 15.0f, k1[e], acc);
                acc = fmaf(32.0f / 9.0f,  k2[e], acc);
                y[e] = fmaf(dt, acc, xr[e]);
            }
            STAGE_BODY(y[0], y[1], y[2], y[3]);
        }

        // stage 5
        LOADK(k3, 3);
        {
            float y[4];
#pragma unroll
            for (int e = 0; e < 4; e++) {
                float acc = (19372.0f / 6561.0f) * k0[e];
                acc = fmaf(-25360.0f / 2187.0f, k1[e], acc);
                acc = fmaf(64448.0f / 6561.0f,  k2[e], acc);
                acc = fmaf(-212.0f / 729.0f,    k3[e], acc);
                y[e] = fmaf(dt, acc, xr[e]);
            }
            STAGE_BODY(y[0], y[1], y[2], y[3]);
        }

        // stage 6
        LOADK(k4, 4);
        {
            float y[4];
#pragma unroll
            for (int e = 0; e < 4; e++) {
                float acc = (9017.0f / 3168.0f) * k0[e];
                acc = fmaf(-355.0f / 33.0f,     k1[e], acc);
                acc = fmaf(46732.0f / 5247.0f,  k2[e], acc);
                acc = fmaf(49.0f / 176.0f,      k3[e], acc);
                acc = fmaf(-5103.0f / 18656.0f, k4[e], acc);
                y[e] = fmaf(dt, acc, xr[e]);
            }
            STAGE_BODY(y[0], y[1], y[2], y[3]);
        }

        // x update
        LOADK(k5, 5);
#pragma unroll
        for (int e = 0; e < 4; e++) {
            float acc = (35.0f / 384.0f) * k0[e];
            acc = fmaf(500.0f / 1113.0f,   k2[e], acc);
            acc = fmaf(125.0f / 192.0f,    k3[e], acc);
            acc = fmaf(-2187.0f / 6784.0f, k4[e], acc);
            acc = fmaf(11.0f / 84.0f,      k5[e], acc);
            xr[e] = fmaf(dt, acc, xr[e]);
        }
        if ((tid >> 1) == b) {
            float4 o;
            o.x = xr[0]; o.y = xr[1]; o.z = xr[2]; o.w = xr[3];
            *reinterpret_cast<float4*>(&xs[(size_t)(step + 1) * NS + j0]) = o;
        }
    }
#undef STAGE_BODY
#undef LOADK
}

// ---------------------------------------------------------------------------
// ys = xs @ C^T  (8192x1024 @ 1024x256) — 64x64 tiled fp32 GEMM.
// ---------------------------------------------------------------------------
__global__ void __launch_bounds__(256)
gemm_ys(const float* __restrict__ xs, const float* __restrict__ C,
        float* __restrict__ ys)
{
    const int BM = 64, BN = 64, BK = 16;
    __shared__ float As[BK][BM];
    __shared__ float Bs[BK][BN];

    const int tid = threadIdx.x;
    const int m0 = blockIdx.y * BM;
    const int n0 = blockIdx.x * BN;
    const int tx = tid & 15;
    const int ty = tid >> 4;

    const int lr = tid >> 2;
    const int lc = (tid & 3) * 4;

    float acc[4][4];
#pragma unroll
    for (int i = 0; i < 4; i++)
#pragma unroll
        for (int j = 0; j < 4; j++) acc[i][j] = 0.0f;

    for (int kk0 = 0; kk0 < NS; kk0 += BK) {
        float4 av = *reinterpret_cast<const float4*>(
            &xs[(size_t)(m0 + lr) * NS + kk0 + lc]);
        float4 bv = *reinterpret_cast<const float4*>(
            &C[(size_t)(n0 + lr) * NS + kk0 + lc]);
        As[lc + 0][lr] = av.x; As[lc + 1][lr] = av.y;
        As[lc + 2][lr] = av.z; As[lc + 3][lr] = av.w;
        Bs[lc + 0][lr] = bv.x; Bs[lc + 1][lr] = bv.y;
        Bs[lc + 2][lr] = bv.z; Bs[lc + 3][lr] = bv.w;
        __syncthreads();

#pragma unroll
        for (int kk = 0; kk < BK; kk++) {
            float ar[4], br[4];
#pragma unroll
            for (int i = 0; i < 4; i++) ar[i] = As[kk][ty * 4 + i];
#pragma unroll
            for (int j = 0; j < 4; j++) br[j] = Bs[kk][tx * 4 + j];
#pragma unroll
            for (int i = 0; i < 4; i++)
#pragma unroll
                for (int j = 0; j < 4; j++)
                    acc[i][j] = fmaf(ar[i], br[j], acc[i][j]);
        }
        __syncthreads();
    }

#pragma unroll
    for (int i = 0; i < 4; i++)
#pragma unroll
        for (int j = 0; j < 4; j++)
            ys[(size_t)(m0 + ty * 4 + i) * NO + n0 + tx * 4 + j] = acc[i][j];
}

extern "C" void kernel_launch(void* const* d_in, const int* in_sizes, int n_in,
                              void* d_out, int out_size)
{
    const float* x0 = (const float*)d_in[0];
    const float* t  = (const float*)d_in[1];
    const float* A  = (const float*)d_in[2];
    const float* C  = (const float*)d_in[3];
    float* out = (float*)d_out;

    // Launches 0,1: pads so launch index 3 (ncu capture slot) = ode_kernel.
    ncu_pad_kernel<<<1, 32>>>();
    ncu_pad_kernel<<<1, 32>>>();

    // Launch 2: reset packed per-block flags (graph-replay safe).
    init_kernel<<<1, 128>>>();

    // Launch 3: ODE integration -> xs = out[0 : NT*NS]
    ode_kernel<<<NBLK, NTHR>>>(x0, t, A, out);

    // Launch 4: output projection -> ys = out[NT*NS : ]
    dim3 g(NO / 64, NT / 64);
    gemm_ys<<<g, 256>>>(out, C, out + (size_t)NT * NS);
}

// round 16
// speedup vs baseline: 4.3291x; 4.3291x over previous
#include <cuda_runtime.h>
#include <cstdint>

#define NS   1024      // n_states
#define NT   8192      // T; NT-1 = 8191 steps
#define NO   256       // n_out
#define NBLK 128       // persistent blocks
#define NTHR 256       // threads per block
#define RPB  8         // rows per block

// Publication entries: one 8-byte {float val (lo), uint tag (hi)} per k row,
// PADDED so each entry owns a full 128B L2 line (PSTR u64s apart). Strong
// poll loads serialize per line at the LTS; spreading gives 128 pollers/line
// (1 per block) instead of R13's ~2048 (the 3x regression there).
// Accessed ONLY with relaxed gpu-scope atomics: single-copy atomic (no
// tearing - R13 proved bit-exact correctness) and unordered (4 poll loads
// MLP into one round trip; acquire would serialize them - the R12 lesson).
#define PSTR 16        // 16 u64 = 128B line per entry
__device__ __align__(16) unsigned long long g_pub[6][NS * PSTR];

__global__ void init_kernel() {
    int i = blockIdx.x * blockDim.x + threadIdx.x;   // 384*256 = 98304 = 6*1024*16
    ((unsigned long long*)g_pub)[i] = 0ull;
}

// Pad launches: ncu captures launch index 3; order [pad, pad, init, ode, gemm]
// puts ode_kernel there (verified R12/R13/R15).
__global__ void ncu_pad_kernel() {}

__device__ __forceinline__ void publish(int S, int R, float v, unsigned tag) {
    unsigned long long pk =
        (unsigned long long)__float_as_uint(v) | ((unsigned long long)tag << 32);
    asm volatile("st.relaxed.gpu.global.u64 [%0], %1;"
                 :: "l"(&g_pub[S][(size_t)R * PSTR]), "l"(pk) : "memory");
}

// Spin until all 4 owned entries of stage-buffer S carry `tag`.
// 4 independent relaxed loads on 4 DISTINCT 128B lines -> MLP'd, one L2
// round trip per sweep, ~128 pollers per line chip-wide.
__device__ __forceinline__ void pollk(int S, int j0, unsigned tag, float k[4]) {
    const unsigned long long* p = &g_pub[S][(size_t)j0 * PSTR];
    unsigned long long e0, e1, e2, e3;
    do {
        asm volatile("ld.relaxed.gpu.global.u64 %0, [%1];"
                     : "=l"(e0) : "l"(p + 0 * PSTR) : "memory");
        asm volatile("ld.relaxed.gpu.global.u64 %0, [%1];"
                     : "=l"(e1) : "l"(p + 1 * PSTR) : "memory");
        asm volatile("ld.relaxed.gpu.global.u64 %0, [%1];"
                     : "=l"(e2) : "l"(p + 2 * PSTR) : "memory");
        asm volatile("ld.relaxed.gpu.global.u64 %0, [%1];"
                     : "=l"(e3) : "l"(p + 3 * PSTR) : "memory");
    } while ((unsigned)(e0 >> 32) != tag || (unsigned)(e1 >> 32) != tag ||
             (unsigned)(e2 >> 32) != tag || (unsigned)(e3 >> 32) != tag);
    k[0] = __uint_as_float((unsigned)e0);
    k[1] = __uint_as_float((unsigned)e1);
    k[2] = __uint_as_float((unsigned)e2);
    k[3] = __uint_as_float((unsigned)e3);
}

__global__ void __launch_bounds__(NTHR, 1)
ode_kernel(const float* __restrict__ x0, const float* __restrict__ t,
           const float* __restrict__ A, float* __restrict__ xs)
{
    __shared__ float ty_sm[2][NS];   // stage-parity double buffer

    const int tid = threadIdx.x;
    const int b   = blockIdx.x;
    const int w   = tid >> 5;        // warp = local row
    const int l   = tid & 31;
    const int R   = b * RPB + w;     // global row this warp produces
    const int j0  = tid * 4;         // 4 owned state indices

    const float dt = __ldg(&t[1]) - __ldg(&t[0]);

    float a[32];
#pragma unroll
    for (int i = 0; i < 32; i++) a[i] = __ldg(&A[R * NS + l + 32 * i]);

    float4 xv = *reinterpret_cast<const float4*>(&x0[j0]);
    float xr[4] = {xv.x, xv.y, xv.z, xv.w};
    float k0[4], k1[4], k2[4], k3[4], k4[4], k5[4];

    if ((tid >> 1) == b) *reinterpret_cast<float4*>(&xs[j0]) = xv;

    unsigned sc = 0;   // stage counter; tag = sc+1 at publish

#define STAGE_BODY(Y0, Y1, Y2, Y3) do {                                     \
        int par = (int)(sc & 1u);                                           \
        float4 tv;                                                          \
        tv.x = tanhf(Y0); tv.y = tanhf(Y1);                                 \
        tv.z = tanhf(Y2); tv.w = tanhf(Y3);                                 \
        *reinterpret_cast<float4*>(&ty_sm[par][j0]) = tv;                   \
        __syncthreads();                                                    \
        float acc0 = 0.f, acc1 = 0.f, acc2 = 0.f, acc3 = 0.f;               \
        const float* ty = ty_sm[par];                                       \
        _Pragma("unroll")                                                   \
        for (int i = 0; i < 32; i += 4) {                                   \
            acc0 = fmaf(a[i + 0], ty[l + 32 * (i + 0)], acc0);              \
            acc1 = fmaf(a[i + 1], ty[l + 32 * (i + 1)], acc1);              \
            acc2 = fmaf(a[i + 2], ty[l + 32 * (i + 2)], acc2);              \
            acc3 = fmaf(a[i + 3], ty[l + 32 * (i + 3)], acc3);              \
        }                                                                   \
        float acc = (acc0 + acc1) + (acc2 + acc3);                          \
        _Pragma("unroll")                                                   \
        for (int o = 16; o > 0; o >>= 1)                                    \
            acc += __shfl_down_sync(0xffffffffu, acc, o);                   \
        sc++;                                                               \
        if (l == 0) publish((int)((sc - 1) % 6u), R, acc, sc);              \
    } while (0)

    for (int step = 0; step < NT - 1; step++) {
        // stage 1: y = x
        STAGE_BODY(xr[0], xr[1], xr[2], xr[3]);

        // stage 2
        pollk(0, j0, sc, k0);
        {
            float y[4];
#pragma unroll
            for (int e = 0; e < 4; e++)
                y[e] = fmaf(dt, 0.2f * k0[e], xr[e]);
            STAGE_BODY(y[0], y[1], y[2], y[3]);
        }

        // stage 3
        pollk(1, j0, sc, k1);
        {
            float y[4];
#pragma unroll
            for (int e = 0; e < 4; e++) {
                float acc = (3.0f / 40.0f) * k0[e];
                acc = fmaf(9.0f / 40.0f, k1[e], acc);
                y[e] = fmaf(dt, acc, xr[e]);
            }
            STAGE_BODY(y[0], y[1], y[2], y[3]);
        }

        // stage 4
        pollk(2, j0, sc, k2);
        {
            float y[4];
#pragma unroll
            for (int e = 0; e < 4; e++) {
                float acc = (44.0f / 45.0f) * k0[e];
                acc = fmaf(-56.0f / 15.0f, k1[e], acc);
                acc = fmaf(32.0f / 9.0f,  k2[e], acc);
                y[e] = fmaf(dt, acc, xr[e]);
            }
            STAGE_BODY(y[0], y[1], y[2], y[3]);
        }

        // stage 5
        pollk(3, j0, sc, k3);
        {
            float y[4];
#pragma unroll
            for (int e = 0; e < 4; e++) {
                float acc = (19372.0f / 6561.0f) * k0[e];
                acc = fmaf(-25360.0f / 2187.0f, k1[e], acc);
                acc = fmaf(64448.0f / 6561.0f,  k2[e], acc);
                acc = fmaf(-212.0f / 729.0f,    k3[e], acc);
                y[e] = fmaf(dt, acc, xr[e]);
            }
            STAGE_BODY(y[0], y[1], y[2], y[3]);
        }

        // stage 6
        pollk(4, j0, sc, k4);
        {
            float y[4];
#pragma unroll
            for (int e = 0; e < 4; e++) {
                float acc = (9017.0f / 3168.0f) * k0[e];
                acc = fmaf(-355.0f / 33.0f,     k1[e], acc);
                acc = fmaf(46732.0f / 5247.0f,  k2[e], acc);
                acc = fmaf(49.0f / 176.0f,      k3[e], acc);
                acc = fmaf(-5103.0f / 18656.0f, k4[e], acc);
                y[e] = fmaf(dt, acc, xr[e]);
            }
            STAGE_BODY(y[0], y[1], y[2], y[3]);
        }

        // x update
        pollk(5, j0, sc, k5);
#pragma unroll
        for (int e = 0; e < 4; e++) {
            float acc = (35.0f / 384.0f) * k0[e];
            acc = fmaf(500.0f / 1113.0f,   k2[e], acc);
            acc = fmaf(125.0f / 192.0f,    k3[e], acc);
            acc = fmaf(-2187.0f / 6784.0f, k4[e], acc);
            acc = fmaf(11.0f / 84.0f,      k5[e], acc);
            xr[e] = fmaf(dt, acc, xr[e]);
        }
        if ((tid >> 1) == b) {
            float4 o;
            o.x = xr[0]; o.y = xr[1]; o.z = xr[2]; o.w = xr[3];
            *reinterpret_cast<float4*>(&xs[(size_t)(step + 1) * NS + j0]) = o;
        }
    }
#undef STAGE_BODY
}

// ---------------------------------------------------------------------------
// ys = xs @ C^T  (8192x1024 @ 1024x256) — 64x64 tiled fp32 GEMM.
// ---------------------------------------------------------------------------
__global__ void __launch_bounds__(256)
gemm_ys(const float* __restrict__ xs, const float* __restrict__ C,
        float* __restrict__ ys)
{
    const int BM = 64, BN = 64, BK = 16;
    __shared__ float As[BK][BM];
    __shared__ float Bs[BK][BN];

    const int tid = threadIdx.x;
    const int m0 = blockIdx.y * BM;
    const int n0 = blockIdx.x * BN;
    const int tx = tid & 15;
    const int ty = tid >> 4;

    const int lr = tid >> 2;
    const int lc = (tid & 3) * 4;

    float acc[4][4];
#pragma unroll
    for (int i = 0; i < 4; i++)
#pragma unroll
        for (int j = 0; j < 4; j++) acc[i][j] = 0.0f;

    for (int kk0 = 0; kk0 < NS; kk0 += BK) {
        float4 av = *reinterpret_cast<const float4*>(
            &xs[(size_t)(m0 + lr) * NS + kk0 + lc]);
        float4 bv = *reinterpret_cast<const float4*>(
            &C[(size_t)(n0 + lr) * NS + kk0 + lc]);
        As[lc + 0][lr] = av.x; As[lc + 1][lr] = av.y;
        As[lc + 2][lr] = av.z; As[lc + 3][lr] = av.w;
        Bs[lc + 0][lr] = bv.x; Bs[lc + 1][lr] = bv.y;
        Bs[lc + 2][lr] = bv.z; Bs[lc + 3][lr] = bv.w;
        __syncthreads();

#pragma unroll
        for (int kk = 0; kk < BK; kk++) {
            float ar[4], br[4];
#pragma unroll
            for (int i = 0; i < 4; i++) ar[i] = As[kk][ty * 4 + i];
#pragma unroll
            for (int j = 0; j < 4; j++) br[j] = Bs[kk][tx * 4 + j];
#pragma unroll
            for (int i = 0; i < 4; i++)
#pragma unroll
                for (int j = 0; j < 4; j++)
                    acc[i][j] = fmaf(ar[i], br[j], acc[i][j]);
        }
        __syncthreads();
    }

#pragma unroll
    for (int i = 0; i < 4; i++)
#pragma unroll
        for (int j = 0; j < 4; j++)
            ys[(size_t)(m0 + ty * 4 + i) * NO + n0 + tx * 4 + j] = acc[i][j];
}

extern "C" void kernel_launch(void* const* d_in, const int* in_sizes, int n_in,
                              void* d_out, int out_size)
{
    const float* x0 = (const float*)d_in[0];
    const float* t  = (const float*)d_in[1];
    const float* A  = (const float*)d_in[2];
    const float* C  = (const float*)d_in[3];
    float* out = (float*)d_out;

    // Launches 0,1: pads so launch index 3 (ncu capture slot) = ode_kernel.
    ncu_pad_kernel<<<1, 32>>>();
    ncu_pad_kernel<<<1, 32>>>();

    // Launch 2: reset all (padded) publication entries (graph-replay safe).
    init_kernel<<<384, 256>>>();

    // Launch 3: ODE integration -> xs = out[0 : NT*NS]
    ode_kernel<<<NBLK, NTHR>>>(x0, t, A, out);

    // Launch 4: output projection -> ys = out[NT*NS : ]
    dim3 g(NO / 64, NT / 64);
    gemm_ys<<<g, 256>>>(out, C, out + (size_t)NT * NS);
}